// round 1
// baseline (speedup 1.0000x reference)
#include <cuda_runtime.h>
#include <math.h>

#define NFFT 4096
#define DDIM 256
#define HDIM 64
#define NB4  4   // BATCH/2 packed complex batches

// ---------------- device scratch (no allocs allowed) ----------------
__device__ float2 g_tw[NFFT];                 // e^{-2*pi*i*k/N}
__device__ float2 g_A [DDIM * NFFT];          // at_roots per (d,l)
__device__ float2 g_Kf[DDIM * NFFT];          // symmetrized kernel spectrum / N
__device__ float2 g_zT[NB4 * DDIM * NFFT];    // packed transposed signals (in/out of FFT)

// ---------------- twiddle table ----------------
__global__ void tw_init_kernel() {
    int k = blockIdx.x * blockDim.x + threadIdx.x;
    if (k < NFFT) {
        double ang = -6.283185307179586476925286766559 * (double)k / (double)NFFT;
        g_tw[k] = make_float2((float)cos(ang), (float)sin(ang));
    }
}

// ---------------- Cauchy / Woodbury kernel spectrum ----------------
// Singularity-free form:
//   u = 1+z, v = 2(1-z), ud = u*delta
//   r_h = ud / (v - lam_h*ud)
//   at  = 2*delta*S00 - 2*delta^2 * u * S01*S10 / (1 + delta*u*S11)
// where S.. = sum_h w.. / q_h, q_h = v - lam_h*ud.
__global__ __launch_bounds__(256) void kfA_kernel(
    const float2* __restrict__ lam, const float2* __restrict__ P,
    const float2* __restrict__ B,   const float2* __restrict__ C,
    const float* __restrict__ log_delta)
{
    __shared__ float2 slam[HDIM];
    __shared__ float4 sw0[HDIM];  // (w00.re, w00.im, w01.re, w01.im)
    __shared__ float4 sw1[HDIM];  // (w10.re, w10.im, w11(real), 0)

    int d = blockIdx.x >> 4;
    int l = ((blockIdx.x & 15) << 8) + threadIdx.x;

    if (threadIdx.x < HDIM) {
        int h = threadIdx.x;
        float2 L_ = lam[h];
        float2 p  = P[h];
        float2 b  = B[d * HDIM + h];
        float2 c  = C[d * HDIM + h];
        slam[h] = L_;
        // w00 = C*B, w01 = C*P
        sw0[h] = make_float4(c.x * b.x - c.y * b.y, c.x * b.y + c.y * b.x,
                             c.x * p.x - c.y * p.y, c.x * p.y + c.y * p.x);
        // w10 = conj(P)*B, w11 = |P|^2 (real)
        sw1[h] = make_float4(p.x * b.x + p.y * b.y, p.x * b.y - p.y * b.x,
                             p.x * p.x + p.y * p.y, 0.0f);
    }
    __syncthreads();

    float delta = __expf(log_delta[d]);
    float2 t = g_tw[l];
    float zr = t.x, zi = -t.y;            // z = e^{+2*pi*i*l/N}
    float ux = 1.0f + zr, uy = zi;        // u = 1+z
    float udx = ux * delta, udy = uy * delta;
    float vx = 2.0f - 2.0f * zr, vy = -2.0f * zi;   // v = 2(1-z)

    float2 s00 = {0.f,0.f}, s01 = {0.f,0.f}, s10 = {0.f,0.f}, s11 = {0.f,0.f};
    #pragma unroll 8
    for (int h = 0; h < HDIM; ++h) {
        float2 L_ = slam[h];
        float qx = vx - (L_.x * udx - L_.y * udy);
        float qy = vy - (L_.x * udy + L_.y * udx);
        float im = __fdividef(1.0f, qx * qx + qy * qy);
        float rr = qx * im, ri = -qy * im;   // 1/q
        float4 a  = sw0[h];
        float4 bw = sw1[h];
        s00.x += a.x * rr - a.y * ri;  s00.y += a.x * ri + a.y * rr;
        s01.x += a.z * rr - a.w * ri;  s01.y += a.z * ri + a.w * rr;
        s10.x += bw.x * rr - bw.y * ri; s10.y += bw.x * ri + bw.y * rr;
        s11.x += bw.z * rr;             s11.y += bw.z * ri;
    }

    // n2 = u * (S01*S10)
    float nx = s01.x * s10.x - s01.y * s10.y;
    float ny = s01.x * s10.y + s01.y * s10.x;
    float n2x = ux * nx - uy * ny;
    float n2y = ux * ny + uy * nx;
    // den = 1 + delta*(u*S11)
    float dnx = 1.0f + delta * (ux * s11.x - uy * s11.y);
    float dny = delta * (ux * s11.y + uy * s11.x);
    float dinv = __fdividef(1.0f, dnx * dnx + dny * dny);
    float d2 = 2.0f * delta * delta;
    float cx_ = d2 * (n2x * dnx + n2y * dny) * dinv;
    float cy_ = d2 * (n2y * dnx - n2x * dny) * dinv;
    g_A[d * NFFT + l] = make_float2(2.0f * delta * s00.x - cx_,
                                    2.0f * delta * s00.y - cy_);
}

// Kf[k] = (A[k] + conj(A[N-k]))/2, folded with 1/N for inverse FFT
__global__ void kf_sym_kernel() {
    int idx = blockIdx.x * blockDim.x + threadIdx.x;
    int d = idx >> 12, l = idx & (NFFT - 1);
    float2 a = g_A[idx];
    float2 b = g_A[(d << 12) | ((NFFT - l) & (NFFT - 1))];
    const float s = 0.5f / (float)NFFT;
    g_Kf[idx] = make_float2(s * (a.x + b.x), s * (a.y - b.y));
}

// ---------------- transpose (B,L,D) -> packed (B4,D,L) complex ----------------
__global__ void t1_kernel(const float* __restrict__ x) {
    __shared__ float2 tile[32][33];
    int b4 = blockIdx.z;
    int d0 = blockIdx.x * 32, l0 = blockIdx.y * 32;
    for (int ly = threadIdx.y; ly < 32; ly += 8) {
        int l = l0 + ly, d = d0 + threadIdx.x;
        float a = x[((b4    ) * NFFT + l) * DDIM + d];
        float b = x[((b4 + 4) * NFFT + l) * DDIM + d];
        tile[ly][threadIdx.x] = make_float2(a, b);
    }
    __syncthreads();
    for (int dy = threadIdx.y; dy < 32; dy += 8) {
        int d = d0 + dy, l = l0 + threadIdx.x;
        g_zT[(b4 * DDIM + d) * NFFT + l] = tile[threadIdx.x][dy];
    }
}

// ---------------- fused fwd FFT * Kf * inv FFT (Stockham radix-4) ----------------
template<int DIR>
__device__ __forceinline__ void fft_stages(float2* X, float2* Y, int tid) {
    float2* src = X;
    float2* dst = Y;
    #pragma unroll
    for (int t = 0; t < 6; ++t) {
        const int sh = 2 * t;
        #pragma unroll
        for (int u = 0; u < 2; ++u) {
            int i = tid + (u << 9);         // [0,1024)
            int p = i >> sh;
            int twi = p << sh;              // p*s
            float2 a = src[i];
            float2 b = src[i + 1024];
            float2 c = src[i + 2048];
            float2 e = src[i + 3072];
            float apcx = a.x + c.x, apcy = a.y + c.y;
            float amcx = a.x - c.x, amcy = a.y - c.y;
            float bpdx = b.x + e.x, bpdy = b.y + e.y;
            float bmdx = b.x - e.x, bmdy = b.y - e.y;
            float2 w1 = g_tw[twi];
            float2 w2 = g_tw[2 * twi];
            float2 w3 = g_tw[3 * twi];
            if (DIR < 0) { w1.y = -w1.y; w2.y = -w2.y; w3.y = -w3.y; }
            float e1x, e1y, e3x, e3y;
            if (DIR > 0) { e1x = amcx + bmdy; e1y = amcy - bmdx;
                           e3x = amcx - bmdy; e3y = amcy + bmdx; }
            else         { e1x = amcx - bmdy; e1y = amcy + bmdx;
                           e3x = amcx + bmdy; e3y = amcy - bmdx; }
            float o0x = apcx + bpdx, o0y = apcy + bpdy;
            float o2x = apcx - bpdx, o2y = apcy - bpdy;
            int s  = 1 << sh;
            int wb = i + 3 * twi;           // i + 3*s*p
            dst[wb]         = make_float2(o0x, o0y);
            dst[wb + s]     = make_float2(w1.x * e1x - w1.y * e1y, w1.x * e1y + w1.y * e1x);
            dst[wb + 2*s]   = make_float2(w2.x * o2x - w2.y * o2y, w2.x * o2y + w2.y * o2x);
            dst[wb + 3*s]   = make_float2(w3.x * e3x - w3.y * e3y, w3.x * e3y + w3.y * e3x);
        }
        __syncthreads();
        float2* tm = src; src = dst; dst = tm;
    }
    // after 6 stages data is back in X
}

__global__ __launch_bounds__(512) void fft_conv_kernel() {
    extern __shared__ float2 sm[];
    float2* X = sm;
    float2* Y = sm + NFFT;
    int bx = blockIdx.x;
    int d  = bx & (DDIM - 1);
    int b4 = bx >> 8;
    int tid = threadIdx.x;
    float2* sig = g_zT + (size_t)(b4 * DDIM + d) * NFFT;

    #pragma unroll
    for (int u = 0; u < 8; ++u) X[tid + 512 * u] = sig[tid + 512 * u];
    __syncthreads();

    fft_stages<1>(X, Y, tid);            // forward, natural order out (in X)

    const float2* kf = g_Kf + d * NFFT;
    #pragma unroll
    for (int u = 0; u < 8; ++u) {
        int i = tid + 512 * u;
        float2 v = X[i];
        float2 k = __ldg(&kf[i]);
        X[i] = make_float2(v.x * k.x - v.y * k.y, v.x * k.y + v.y * k.x);
    }
    __syncthreads();

    fft_stages<-1>(X, Y, tid);           // inverse (1/N folded into Kf)

    #pragma unroll
    for (int u = 0; u < 8; ++u) sig[tid + 512 * u] = X[tid + 512 * u];
}

// ---------------- untranspose + split Re/Im + D*x ----------------
__global__ void t2_kernel(const float* __restrict__ x, const float* __restrict__ Dp,
                          float* __restrict__ y) {
    __shared__ float2 tile[32][33];
    int b4 = blockIdx.z;
    int d0 = blockIdx.x * 32, l0 = blockIdx.y * 32;
    for (int dy = threadIdx.y; dy < 32; dy += 8) {
        int d = d0 + dy, l = l0 + threadIdx.x;
        tile[dy][threadIdx.x] = g_zT[(b4 * DDIM + d) * NFFT + l];
    }
    __syncthreads();
    for (int ly = threadIdx.y; ly < 32; ly += 8) {
        int l = l0 + ly;
        int d = d0 + threadIdx.x;
        float2 v = tile[threadIdx.x][ly];
        float dd = Dp[d];
        int i0 = ((b4    ) * NFFT + l) * DDIM + d;
        int i1 = ((b4 + 4) * NFFT + l) * DDIM + d;
        y[i0] = v.x + dd * x[i0];
        y[i1] = v.y + dd * x[i1];
    }
}

// ---------------- launcher ----------------
extern "C" void kernel_launch(void* const* d_in, const int* in_sizes, int n_in,
                              void* d_out, int out_size) {
    const float*  x   = (const float*)d_in[0];
    const float2* lam = (const float2*)d_in[1];
    const float2* P   = (const float2*)d_in[2];
    const float2* B   = (const float2*)d_in[3];
    const float2* C   = (const float2*)d_in[4];
    const float*  Dp  = (const float*)d_in[5];
    const float*  ld  = (const float*)d_in[6];
    float* y = (float*)d_out;

    cudaFuncSetAttribute(fft_conv_kernel,
                         cudaFuncAttributeMaxDynamicSharedMemorySize, 2 * NFFT * sizeof(float2));

    tw_init_kernel<<<8, 512>>>();
    kfA_kernel<<<DDIM * 16, 256>>>(lam, P, B, C, ld);
    kf_sym_kernel<<<4096, 256>>>();

    dim3 tb(32, 8);
    t1_kernel<<<dim3(DDIM / 32, NFFT / 32, NB4), tb>>>(x);
    fft_conv_kernel<<<NB4 * DDIM, 512, 2 * NFFT * sizeof(float2)>>>();
    t2_kernel<<<dim3(DDIM / 32, NFFT / 32, NB4), tb>>>(x, Dp, y);
}

// round 2
// speedup vs baseline: 1.4630x; 1.4630x over previous
#include <cuda_runtime.h>
#include <math.h>

#define NFFT 4096
#define DDIM 256
#define HDIM 64
#define NB4  4   // BATCH/2 packed complex batches

// ---------------- device scratch ----------------
__device__ float2 g_tw[NFFT];                 // e^{-2*pi*i*k/N}
__device__ float2 g_Kf[DDIM * NFFT];          // Hermitian kernel spectrum / N
__device__ float2 g_zT[NB4 * DDIM * NFFT];    // packed transposed signals
__device__ float4 g_w0[DDIM * HDIM];          // (w00.re, w00.im, w01.re, w01.im) with Chat
__device__ float4 g_w1[DDIM * HDIM];          // (w10.re, w10.im, w11(real), 0)

// ---------------- twiddle table ----------------
__global__ void tw_init_kernel() {
    int k = blockIdx.x * blockDim.x + threadIdx.x;
    if (k < NFFT) {
        double ang = -6.283185307179586476925286766559 * (double)k / (double)NFFT;
        g_tw[k] = make_float2((float)cos(ang), (float)sin(ang));
    }
}

// ---------------- weight prep: conj-pairing + Hermitian-symmetrized C ----------------
__global__ __launch_bounds__(256) void weight_kernel(
    const float2* __restrict__ lam, const float2* __restrict__ P,
    const float2* __restrict__ B,   const float2* __restrict__ C)
{
    __shared__ int spair[HDIM];
    int tid = threadIdx.x;
    if (tid < HDIM) {
        float2 L = lam[tid];
        float best = 3.4e38f; int bi = tid;
        for (int j = 0; j < HDIM; ++j) {
            float2 M = lam[j];
            float dx = M.x - L.x, dy = M.y + L.y;   // |lam_j - conj(lam_tid)|^2
            float e = dx * dx + dy * dy;
            if (e < best) { best = e; bi = j; }
        }
        spair[tid] = bi;
    }
    __syncthreads();
    int idx = blockIdx.x * 256 + tid;          // d*H + h, 16384 total
    int h = idx & (HDIM - 1); int d = idx >> 6;
    float2 c  = C[idx];
    float2 c2 = C[(d << 6) | spair[h]];
    float chx = 0.5f * (c.x + c2.x);
    float chy = 0.5f * (c.y - c2.y);           // Chat = (C_h + conj(C_hbar))/2
    float2 b = B[idx];
    float2 p = P[h];
    g_w0[idx] = make_float4(chx * b.x - chy * b.y, chx * b.y + chy * b.x,
                            chx * p.x - chy * p.y, chx * p.y + chy * p.x);
    g_w1[idx] = make_float4(p.x * b.x + p.y * b.y, p.x * b.y - p.y * b.x,
                            p.x * p.x + p.y * p.y, 0.0f);
}

// ---------------- direct Hermitian kernel spectrum (half the points) ----------------
// g-form (reference form): g = 2(1-z)/((1+z)*delta), k.. = sum_h w../(g-lam_h)
// at = (2/u)*(k00 - k01*k10/(1+k11));  Nyquist (z=-1): at = 2*delta*sum(w00)/4
__global__ __launch_bounds__(256) void kf_kernel(
    const float2* __restrict__ lam, const float* __restrict__ log_delta)
{
    __shared__ float2 sl[HDIM];
    __shared__ float4 s0[HDIM];
    __shared__ float4 s1[HDIM];
    int d = blockIdx.y;
    int tid = threadIdx.x;
    if (tid < HDIM) {
        sl[tid] = lam[tid];
        s0[tid] = g_w0[(d << 6) + tid];
        s1[tid] = g_w1[(d << 6) + tid];
    }
    __syncthreads();

    int l = blockIdx.x * 256 + tid;            // [0, 2303]; active if l <= 2048
    bool active = (l <= 2048);
    bool nyq = (l == 2048);
    float delta = __expf(log_delta[d]);
    float2 t = g_tw[l & (NFFT - 1)];
    float zr = t.x, zi = -t.y;                 // z = e^{+2*pi*i*l/N}
    float ux = 1.0f + zr, uy = zi;             // u = 1+z
    float vx = 2.0f - 2.0f * zr, vy = -2.0f * zi;
    float udx = ux * delta, udy = uy * delta;
    float dn = udx * udx + udy * udy;
    float di = __fdividef(1.0f, fmaxf(dn, 1e-30f));
    float gx = (vx * udx + vy * udy) * di;     // g = v/(u*delta)
    float gy = (vy * udx - vx * udy) * di;

    float s00x=0.f,s00y=0.f,s01x=0.f,s01y=0.f,s10x=0.f,s10y=0.f,s11x=0.f,s11y=0.f;
    #pragma unroll 8
    for (int h = 0; h < HDIM; ++h) {
        float2 L = sl[h];
        float qx = gx - L.x, qy = gy - L.y;
        float im = __fdividef(1.0f, qx * qx + qy * qy);
        float rr = qx * im, ri = -qy * im;
        if (nyq) { rr = 0.25f; ri = 0.0f; }    // z=-1: q_safe = 4
        float4 a = s0[h]; float4 b = s1[h];
        s00x += a.x * rr - a.y * ri;  s00y += a.x * ri + a.y * rr;
        s01x += a.z * rr - a.w * ri;  s01y += a.z * ri + a.w * rr;
        s10x += b.x * rr - b.y * ri;  s10y += b.x * ri + b.y * rr;
        s11x += b.z * rr;             s11y += b.z * ri;
    }

    float nx  = s01x * s10x - s01y * s10y;
    float ny  = s01x * s10y + s01y * s10x;
    float dnx = 1.0f + s11x, dny = s11y;
    float ddi = __fdividef(1.0f, dnx * dnx + dny * dny);
    float cx  = (nx * dnx + ny * dny) * ddi;
    float cy  = (ny * dnx - nx * dny) * ddi;
    float k0x = s00x - cx, k0y = s00y - cy;
    float ui  = __fdividef(2.0f, ux * ux + uy * uy);
    float ax  = (k0x * ux + k0y * uy) * ui;
    float ay  = (k0y * ux - k0x * uy) * ui;
    if (nyq) { ax = 2.0f * delta * s00x; ay = 0.0f; }
    const float sc = 1.0f / (float)NFFT;       // fold 1/N of inverse FFT
    ax *= sc; ay *= sc;
    if (l == 0) ay = 0.0f;
    if (active) {
        g_Kf[(d << 12) + l] = make_float2(ax, ay);
        if (l > 0 && l < 2048)
            g_Kf[(d << 12) + (NFFT - l)] = make_float2(ax, -ay);
    }
}

// ---------------- transpose (B,L,D) -> packed (B4,D,L) complex, float4 ----------------
__global__ __launch_bounds__(256) void t1_kernel(const float* __restrict__ x) {
    __shared__ float2 tile[32][34];
    int b4 = blockIdx.z;
    int d0 = blockIdx.x << 5, l0 = blockIdx.y << 5;
    int tid = threadIdx.x;
    const float4* x4 = (const float4*)x;
    {
        int l = tid >> 3, d4 = tid & 7;
        int base0 = ((b4 * NFFT) + l0 + l) * (DDIM / 4) + (d0 >> 2) + d4;
        int base1 = base0 + 4 * NFFT * (DDIM / 4);
        float4 A  = x4[base0];
        float4 Bv = x4[base1];
        float4* row = (float4*)&tile[l][d4 << 2];
        row[0] = make_float4(A.x, Bv.x, A.y, Bv.y);
        row[1] = make_float4(A.z, Bv.z, A.w, Bv.w);
    }
    __syncthreads();
    float4* zT4 = (float4*)g_zT;
    #pragma unroll
    for (int u = 0; u < 2; ++u) {
        int m = tid + (u << 8);
        int dd = m >> 4, lp = m & 15;
        float2 t0 = tile[2 * lp][dd];
        float2 t1 = tile[2 * lp + 1][dd];
        zT4[(((b4 * DDIM) + d0 + dd) * NFFT + l0 + 2 * lp) >> 1]
            = make_float4(t0.x, t0.y, t1.x, t1.y);
    }
}

// ---------------- radix-8 Stockham FFT helpers ----------------
__device__ __forceinline__ float2 cmulf(float2 a, float2 b) {
    return make_float2(a.x * b.x - a.y * b.y, a.x * b.y + a.y * b.x);
}
#define SWZ(m) ((m) ^ (((m) >> 4) & 7))

template<int DIR>
__device__ __forceinline__ void bfly8(float2 a[8]) {
    const float S2 = 0.70710678118654752440f;
    float2 b0, b1, b2, b3, c0, c1, c2, c3;
    b0.x=a[0].x+a[4].x; b0.y=a[0].y+a[4].y;  c0.x=a[0].x-a[4].x; c0.y=a[0].y-a[4].y;
    b1.x=a[1].x+a[5].x; b1.y=a[1].y+a[5].y;  c1.x=a[1].x-a[5].x; c1.y=a[1].y-a[5].y;
    b2.x=a[2].x+a[6].x; b2.y=a[2].y+a[6].y;  c2.x=a[2].x-a[6].x; c2.y=a[2].y-a[6].y;
    b3.x=a[3].x+a[7].x; b3.y=a[3].y+a[7].y;  c3.x=a[3].x-a[7].x; c3.y=a[3].y-a[7].y;
    float2 tc1, tc2, tc3;
    if (DIR > 0) {
        tc1 = make_float2(S2 * (c1.x + c1.y),  S2 * (c1.y - c1.x));   // *(1-i)/sqrt2
        tc2 = make_float2(c2.y, -c2.x);                                // *(-i)
        tc3 = make_float2(S2 * (c3.y - c3.x), -S2 * (c3.x + c3.y));   // *(-1-i)/sqrt2
    } else {
        tc1 = make_float2(S2 * (c1.x - c1.y),  S2 * (c1.y + c1.x));   // *(1+i)/sqrt2
        tc2 = make_float2(-c2.y, c2.x);                                // *(+i)
        tc3 = make_float2(-S2 * (c3.x + c3.y), S2 * (c3.x - c3.y));   // *(-1+i)/sqrt2
    }
    float2 p0 = make_float2(b0.x + b2.x, b0.y + b2.y);
    float2 p1 = make_float2(b0.x - b2.x, b0.y - b2.y);
    float2 p2 = make_float2(b1.x + b3.x, b1.y + b3.y);
    float2 p3 = make_float2(b1.x - b3.x, b1.y - b3.y);
    float2 q0 = make_float2(c0.x + tc2.x, c0.y + tc2.y);
    float2 q1 = make_float2(c0.x - tc2.x, c0.y - tc2.y);
    float2 q2 = make_float2(tc1.x + tc3.x, tc1.y + tc3.y);
    float2 q3 = make_float2(tc1.x - tc3.x, tc1.y - tc3.y);
    float2 jp3 = (DIR > 0) ? make_float2(p3.y, -p3.x) : make_float2(-p3.y, p3.x);
    float2 jq3 = (DIR > 0) ? make_float2(q3.y, -q3.x) : make_float2(-q3.y, q3.x);
    a[0] = make_float2(p0.x + p2.x, p0.y + p2.y);
    a[4] = make_float2(p0.x - p2.x, p0.y - p2.y);
    a[2] = make_float2(p1.x + jp3.x, p1.y + jp3.y);
    a[6] = make_float2(p1.x - jp3.x, p1.y - jp3.y);
    a[1] = make_float2(q0.x + q2.x, q0.y + q2.y);
    a[5] = make_float2(q0.x - q2.x, q0.y - q2.y);
    a[3] = make_float2(q1.x + jq3.x, q1.y + jq3.y);
    a[7] = make_float2(q1.x - jq3.x, q1.y - jq3.y);
}

template<int DIR, int TSH>
__device__ __forceinline__ void stage_tw_store(float2* dst, float2 a[8], int i) {
    const int s = 1 << TSH;
    int ps = (i >> TSH) << TSH;
    if (TSH < 9) {
        #pragma unroll
        for (int k = 1; k < 8; ++k) {
            float2 w = g_tw[k * ps];
            if (DIR < 0) w.y = -w.y;
            a[k] = cmulf(a[k], w);
        }
    }
    int base = (i & (s - 1)) + (ps << 3);
    #pragma unroll
    for (int k = 0; k < 8; ++k) dst[SWZ(base + (k << TSH))] = a[k];
}

__global__ __launch_bounds__(512) void fft_conv8_kernel() {
    extern __shared__ float2 sm[];
    float2* S0 = sm;
    float2* S1 = sm + NFFT;
    int d  = blockIdx.x & (DDIM - 1);
    int i  = threadIdx.x;
    float2* sig = g_zT + (size_t)blockIdx.x * NFFT;   // blockIdx.x = b4*256 + d
    float2 a[8];

    // ---- forward: F0 (global), F1..F3 (smem) ----
    #pragma unroll
    for (int j = 0; j < 8; ++j) a[j] = sig[i + j * 512];
    bfly8<1>(a); stage_tw_store<1, 0>(S0, a, i);
    __syncthreads();
    #pragma unroll
    for (int j = 0; j < 8; ++j) a[j] = S0[SWZ(i + j * 512)];
    bfly8<1>(a); stage_tw_store<1, 3>(S1, a, i);
    __syncthreads();
    #pragma unroll
    for (int j = 0; j < 8; ++j) a[j] = S1[SWZ(i + j * 512)];
    bfly8<1>(a); stage_tw_store<1, 6>(S0, a, i);
    __syncthreads();
    #pragma unroll
    for (int j = 0; j < 8; ++j) a[j] = S0[SWZ(i + j * 512)];
    bfly8<1>(a); stage_tw_store<1, 9>(S1, a, i);
    __syncthreads();

    // ---- inverse: I0 folds Kf multiply into the load ----
    const float2* kf = g_Kf + (d << 12);
    #pragma unroll
    for (int j = 0; j < 8; ++j) {
        int m = i + j * 512;                     // natural-order bin
        a[j] = cmulf(S1[SWZ(m)], kf[m]);
    }
    bfly8<-1>(a); stage_tw_store<-1, 0>(S0, a, i);
    __syncthreads();
    #pragma unroll
    for (int j = 0; j < 8; ++j) a[j] = S0[SWZ(i + j * 512)];
    bfly8<-1>(a); stage_tw_store<-1, 3>(S1, a, i);
    __syncthreads();
    #pragma unroll
    for (int j = 0; j < 8; ++j) a[j] = S1[SWZ(i + j * 512)];
    bfly8<-1>(a); stage_tw_store<-1, 6>(S0, a, i);
    __syncthreads();
    #pragma unroll
    for (int j = 0; j < 8; ++j) a[j] = S0[SWZ(i + j * 512)];
    bfly8<-1>(a);
    // last stage: s=512, p=0 -> no twiddles, write global directly
    #pragma unroll
    for (int k = 0; k < 8; ++k) sig[i + k * 512] = a[k];
}

// ---------------- untranspose + split Re/Im + D*x, float4 ----------------
__global__ __launch_bounds__(256) void t2_kernel(const float* __restrict__ x,
                                                 const float* __restrict__ Dp,
                                                 float* __restrict__ y) {
    __shared__ float2 tile[32][34];
    int b4 = blockIdx.z;
    int d0 = blockIdx.x << 5, l0 = blockIdx.y << 5;
    int tid = threadIdx.x;
    const float4* zT4 = (const float4*)g_zT;
    #pragma unroll
    for (int u = 0; u < 2; ++u) {
        int m = tid + (u << 8);
        int dd = m >> 4, lp = m & 15;
        float4 v = zT4[(((b4 * DDIM) + d0 + dd) * NFFT + l0 + 2 * lp) >> 1];
        tile[2 * lp][dd]     = make_float2(v.x, v.y);
        tile[2 * lp + 1][dd] = make_float2(v.z, v.w);
    }
    __syncthreads();
    {
        int l = tid >> 3, d4 = tid & 7;
        const float4* x4 = (const float4*)x;
        const float4* D4 = (const float4*)Dp;
        float4 DD = D4[(d0 >> 2) + d4];
        int base0 = ((b4 * NFFT) + l0 + l) * (DDIM / 4) + (d0 >> 2) + d4;
        int base1 = base0 + 4 * NFFT * (DDIM / 4);
        float4 X0 = x4[base0], X1 = x4[base1];
        const float4* row = (const float4*)&tile[l][d4 << 2];
        float4 r0 = row[0];   // (t0.x, t0.y, t1.x, t1.y)
        float4 r1 = row[1];   // (t2.x, t2.y, t3.x, t3.y)
        float4* y4 = (float4*)y;
        y4[base0] = make_float4(r0.x + DD.x * X0.x, r0.z + DD.y * X0.y,
                                r1.x + DD.z * X0.z, r1.z + DD.w * X0.w);
        y4[base1] = make_float4(r0.y + DD.x * X1.x, r0.w + DD.y * X1.y,
                                r1.y + DD.z * X1.z, r1.w + DD.w * X1.w);
    }
}

// ---------------- launcher ----------------
extern "C" void kernel_launch(void* const* d_in, const int* in_sizes, int n_in,
                              void* d_out, int out_size) {
    const float*  x   = (const float*)d_in[0];
    const float2* lam = (const float2*)d_in[1];
    const float2* P   = (const float2*)d_in[2];
    const float2* B   = (const float2*)d_in[3];
    const float2* C   = (const float2*)d_in[4];
    const float*  Dp  = (const float*)d_in[5];
    const float*  ld  = (const float*)d_in[6];
    float* y = (float*)d_out;

    cudaFuncSetAttribute(fft_conv8_kernel,
                         cudaFuncAttributeMaxDynamicSharedMemorySize,
                         2 * NFFT * sizeof(float2));

    tw_init_kernel<<<8, 512>>>();
    weight_kernel<<<DDIM * HDIM / 256, 256>>>(lam, P, B, C);
    kf_kernel<<<dim3(9, DDIM), 256>>>(lam, ld);

    dim3 tb(256);
    t1_kernel<<<dim3(DDIM / 32, NFFT / 32, NB4), tb>>>(x);
    fft_conv8_kernel<<<NB4 * DDIM, 512, 2 * NFFT * sizeof(float2)>>>();
    t2_kernel<<<dim3(DDIM / 32, NFFT / 32, NB4), tb>>>(x, Dp, y);
}

// round 3
// speedup vs baseline: 1.6569x; 1.1325x over previous
#include <cuda_runtime.h>
#include <math.h>

#define NFFT 4096
#define DDIM 256
#define HDIM 64
#define NB4  4   // BATCH/2 packed complex batches

typedef unsigned long long u64;

// ---------------- device scratch ----------------
__device__ float2 g_tw[NFFT];                 // e^{-2*pi*i*k/N}
__device__ float2 g_Kf[DDIM * NFFT];          // Hermitian kernel spectrum / N
__device__ float2 g_zT[NB4 * DDIM * NFFT];    // packed transposed signals
__device__ float4 g_wA[DDIM * HDIM];          // (w00x, w00x, -w00y, w00y)
__device__ float4 g_wB[DDIM * HDIM];          // (w01x, w01x, -w01y, w01y)
__device__ float4 g_wC[DDIM * HDIM];          // (w10x, w10x, -w10y, w10y)
__device__ float2 g_wW[DDIM * HDIM];          // (w11, w11)

// ---------------- f32x2 packed helpers ----------------
__device__ __forceinline__ u64 pk2(float a, float b) {
    u64 r; asm("mov.b64 %0,{%1,%2};" : "=l"(r) : "f"(a), "f"(b)); return r;
}
__device__ __forceinline__ void upk2(u64 v, float& a, float& b) {
    asm("mov.b64 {%0,%1},%2;" : "=f"(a), "=f"(b) : "l"(v));
}
__device__ __forceinline__ u64 fma2(u64 a, u64 b, u64 c) {
    u64 d; asm("fma.rn.f32x2 %0,%1,%2,%3;" : "=l"(d) : "l"(a), "l"(b), "l"(c)); return d;
}
__device__ __forceinline__ u64 add2(u64 a, u64 b) {
    u64 d; asm("add.rn.f32x2 %0,%1,%2;" : "=l"(d) : "l"(a), "l"(b)); return d;
}

// ---------------- twiddle table ----------------
__global__ void tw_init_kernel() {
    int k = blockIdx.x * blockDim.x + threadIdx.x;
    if (k < NFFT) {
        double ang = -6.283185307179586476925286766559 * (double)k / (double)NFFT;
        g_tw[k] = make_float2((float)cos(ang), (float)sin(ang));
    }
}

// ---------------- weight prep: conj-pairing + Hermitian-symmetrized C, packed ----------------
__global__ __launch_bounds__(256) void weight_kernel(
    const float2* __restrict__ lam, const float2* __restrict__ P,
    const float2* __restrict__ B,   const float2* __restrict__ C)
{
    __shared__ int spair[HDIM];
    int tid = threadIdx.x;
    if (tid < HDIM) {
        float2 L = lam[tid];
        float best = 3.4e38f; int bi = tid;
        for (int j = 0; j < HDIM; ++j) {
            float2 M = lam[j];
            float dx = M.x - L.x, dy = M.y + L.y;   // |lam_j - conj(lam_tid)|^2
            float e = dx * dx + dy * dy;
            if (e < best) { best = e; bi = j; }
        }
        spair[tid] = bi;
    }
    __syncthreads();
    int idx = blockIdx.x * 256 + tid;          // d*H + h
    int h = idx & (HDIM - 1); int d = idx >> 6;
    float2 c  = C[idx];
    float2 c2 = C[(d << 6) | spair[h]];
    float chx = 0.5f * (c.x + c2.x);
    float chy = 0.5f * (c.y - c2.y);           // Chat = (C_h + conj(C_hbar))/2
    float2 b = B[idx];
    float2 p = P[h];
    float w00x = chx * b.x - chy * b.y, w00y = chx * b.y + chy * b.x;
    float w01x = chx * p.x - chy * p.y, w01y = chx * p.y + chy * p.x;
    float w10x = p.x * b.x + p.y * b.y, w10y = p.x * b.y - p.y * b.x;
    float w11  = p.x * p.x + p.y * p.y;
    g_wA[idx] = make_float4(w00x, w00x, -w00y, w00y);
    g_wB[idx] = make_float4(w01x, w01x, -w01y, w01y);
    g_wC[idx] = make_float4(w10x, w10x, -w10y, w10y);
    g_wW[idx] = make_float2(w11, w11);
}

// ---------------- Hermitian kernel spectrum, l in [0,2048), f32x2 packed ----------------
__global__ __launch_bounds__(256) void kf_kernel(
    const float2* __restrict__ lam, const float* __restrict__ log_delta)
{
    __shared__ float2 snl[HDIM];
    __shared__ float4 sA[HDIM], sB[HDIM], sC[HDIM];
    __shared__ float2 sW[HDIM];
    int d = blockIdx.y;
    int tid = threadIdx.x;
    if (tid < HDIM) {
        float2 L = lam[tid];
        snl[tid] = make_float2(-L.x, -L.y);
        sA[tid] = g_wA[(d << 6) + tid];
        sB[tid] = g_wB[(d << 6) + tid];
        sC[tid] = g_wC[(d << 6) + tid];
        sW[tid] = g_wW[(d << 6) + tid];
    }
    __syncthreads();

    int l = blockIdx.x * 256 + tid;            // [0, 2048)
    float delta = __expf(log_delta[d]);
    float2 t = g_tw[l];
    float zr = t.x, zi = -t.y;                 // z = e^{+2*pi*i*l/N}
    float ux = 1.0f + zr, uy = zi;             // u = 1+z  (never 0 for l<2048)
    float vx = 2.0f - 2.0f * zr, vy = -2.0f * zi;
    float udx = ux * delta, udy = uy * delta;
    float di = __fdividef(1.0f, udx * udx + udy * udy);
    float gx = (vx * udx + vy * udy) * di;     // g = v/(u*delta)
    float gy = (vy * udx - vx * udy) * di;
    u64 g2 = pk2(gx, gy);

    u64 s00 = 0ull, s01 = 0ull, s10 = 0ull, s11 = 0ull;
    const u64* pnl        = (const u64*)snl;
    const ulonglong2* pA  = (const ulonglong2*)sA;
    const ulonglong2* pB  = (const ulonglong2*)sB;
    const ulonglong2* pC  = (const ulonglong2*)sC;
    const u64* pW         = (const u64*)sW;
    #pragma unroll 16
    for (int h = 0; h < HDIM; ++h) {
        u64 q = add2(g2, pnl[h]);
        float qx, qy; upk2(q, qx, qy);
        float im = __fdividef(1.0f, qx * qx + qy * qy);
        float rr = qx * im, ri = -qy * im;     // 1/(g-lam) = (rr, ri)
        u64 rA = pk2(rr, ri);
        u64 rB = pk2(ri, rr);
        ulonglong2 A = pA[h];  s00 = fma2(A.x, rA, s00); s00 = fma2(A.y, rB, s00);
        ulonglong2 Bv = pB[h]; s01 = fma2(Bv.x, rA, s01); s01 = fma2(Bv.y, rB, s01);
        ulonglong2 Cv = pC[h]; s10 = fma2(Cv.x, rA, s10); s10 = fma2(Cv.y, rB, s10);
        s11 = fma2(pW[h], rA, s11);
    }
    float s00x, s00y, s01x, s01y, s10x, s10y, s11x, s11y;
    upk2(s00, s00x, s00y); upk2(s01, s01x, s01y);
    upk2(s10, s10x, s10y); upk2(s11, s11x, s11y);

    float nx  = s01x * s10x - s01y * s10y;
    float ny  = s01x * s10y + s01y * s10x;
    float dnx = 1.0f + s11x, dny = s11y;
    float ddi = __fdividef(1.0f, dnx * dnx + dny * dny);
    float cx  = (nx * dnx + ny * dny) * ddi;
    float cy  = (ny * dnx - nx * dny) * ddi;
    float k0x = s00x - cx, k0y = s00y - cy;
    float ui  = __fdividef(2.0f, ux * ux + uy * uy);
    float ax  = (k0x * ux + k0y * uy) * ui;
    float ay  = (k0y * ux - k0x * uy) * ui;
    const float sc = 1.0f / (float)NFFT;       // fold 1/N of inverse FFT
    ax *= sc; ay *= sc;
    if (l == 0) ay = 0.0f;
    g_Kf[(d << 12) + l] = make_float2(ax, ay);
    if (l > 0)
        g_Kf[(d << 12) + (NFFT - l)] = make_float2(ax, -ay);
}

// Nyquist bin (z = -1): at = 0.5*delta*sum_h Re(w00)
__global__ void kf_nyq_kernel(const float* __restrict__ log_delta) {
    __shared__ float red[2];
    int d = blockIdx.x;
    int h = threadIdx.x;                      // 64 threads
    float v = g_wA[(d << 6) + h].x;
    #pragma unroll
    for (int o = 16; o > 0; o >>= 1) v += __shfl_down_sync(0xffffffffu, v, o);
    if ((h & 31) == 0) red[h >> 5] = v;
    __syncthreads();
    if (h == 0) {
        float s = red[0] + red[1];
        float delta = __expf(log_delta[d]);
        g_Kf[(d << 12) + 2048] = make_float2(0.5f * delta * s * (1.0f / (float)NFFT), 0.0f);
    }
}

// ---------------- transpose (B,L,D) -> packed (B4,D,L) complex ----------------
__global__ __launch_bounds__(256) void t1_kernel(const float* __restrict__ x) {
    __shared__ float2 tile[32][33];
    int b4 = blockIdx.z;
    int d0 = blockIdx.x << 5, l0 = blockIdx.y << 5;
    int tid = threadIdx.x;
    const float4* x4 = (const float4*)x;
    {
        int l = tid >> 3, d4 = tid & 7;
        int base0 = ((b4 * NFFT) + l0 + l) * (DDIM / 4) + (d0 >> 2) + d4;
        int base1 = base0 + 4 * NFFT * (DDIM / 4);
        float4 A  = x4[base0];
        float4 Bv = x4[base1];
        tile[l][4 * d4 + 0] = make_float2(A.x, Bv.x);
        tile[l][4 * d4 + 1] = make_float2(A.y, Bv.y);
        tile[l][4 * d4 + 2] = make_float2(A.z, Bv.z);
        tile[l][4 * d4 + 3] = make_float2(A.w, Bv.w);
    }
    __syncthreads();
    float4* zT4 = (float4*)g_zT;
    #pragma unroll
    for (int u = 0; u < 2; ++u) {
        int m = tid + (u << 8);
        int dd = m >> 4, lp = m & 15;
        float2 t0 = tile[2 * lp][dd];
        float2 t1 = tile[2 * lp + 1][dd];
        zT4[(((b4 * DDIM) + d0 + dd) * NFFT + l0 + 2 * lp) >> 1]
            = make_float4(t0.x, t0.y, t1.x, t1.y);
    }
}

// ---------------- radix-8 Stockham FFT helpers ----------------
__device__ __forceinline__ float2 cmulf(float2 a, float2 b) {
    return make_float2(a.x * b.x - a.y * b.y, a.x * b.y + a.y * b.x);
}
#define SWZ(m) ((m) ^ (((m) >> 4) & 7))

template<int DIR>
__device__ __forceinline__ void bfly8(float2 a[8]) {
    const float S2 = 0.70710678118654752440f;
    float2 b0, b1, b2, b3, c0, c1, c2, c3;
    b0.x=a[0].x+a[4].x; b0.y=a[0].y+a[4].y;  c0.x=a[0].x-a[4].x; c0.y=a[0].y-a[4].y;
    b1.x=a[1].x+a[5].x; b1.y=a[1].y+a[5].y;  c1.x=a[1].x-a[5].x; c1.y=a[1].y-a[5].y;
    b2.x=a[2].x+a[6].x; b2.y=a[2].y+a[6].y;  c2.x=a[2].x-a[6].x; c2.y=a[2].y-a[6].y;
    b3.x=a[3].x+a[7].x; b3.y=a[3].y+a[7].y;  c3.x=a[3].x-a[7].x; c3.y=a[3].y-a[7].y;
    float2 tc1, tc2, tc3;
    if (DIR > 0) {
        tc1 = make_float2(S2 * (c1.x + c1.y),  S2 * (c1.y - c1.x));
        tc2 = make_float2(c2.y, -c2.x);
        tc3 = make_float2(S2 * (c3.y - c3.x), -S2 * (c3.x + c3.y));
    } else {
        tc1 = make_float2(S2 * (c1.x - c1.y),  S2 * (c1.y + c1.x));
        tc2 = make_float2(-c2.y, c2.x);
        tc3 = make_float2(-S2 * (c3.x + c3.y), S2 * (c3.x - c3.y));
    }
    float2 p0 = make_float2(b0.x + b2.x, b0.y + b2.y);
    float2 p1 = make_float2(b0.x - b2.x, b0.y - b2.y);
    float2 p2 = make_float2(b1.x + b3.x, b1.y + b3.y);
    float2 p3 = make_float2(b1.x - b3.x, b1.y - b3.y);
    float2 q0 = make_float2(c0.x + tc2.x, c0.y + tc2.y);
    float2 q1 = make_float2(c0.x - tc2.x, c0.y - tc2.y);
    float2 q2 = make_float2(tc1.x + tc3.x, tc1.y + tc3.y);
    float2 q3 = make_float2(tc1.x - tc3.x, tc1.y - tc3.y);
    float2 jp3 = (DIR > 0) ? make_float2(p3.y, -p3.x) : make_float2(-p3.y, p3.x);
    float2 jq3 = (DIR > 0) ? make_float2(q3.y, -q3.x) : make_float2(-q3.y, q3.x);
    a[0] = make_float2(p0.x + p2.x, p0.y + p2.y);
    a[4] = make_float2(p0.x - p2.x, p0.y - p2.y);
    a[2] = make_float2(p1.x + jp3.x, p1.y + jp3.y);
    a[6] = make_float2(p1.x - jp3.x, p1.y - jp3.y);
    a[1] = make_float2(q0.x + q2.x, q0.y + q2.y);
    a[5] = make_float2(q0.x - q2.x, q0.y - q2.y);
    a[3] = make_float2(q1.x + jq3.x, q1.y + jq3.y);
    a[7] = make_float2(q1.x - jq3.x, q1.y - jq3.y);
}

template<int DIR, int TSH>
__device__ __forceinline__ void stage_tw_store(float2* dst, float2 a[8], int i) {
    const int s = 1 << TSH;
    int ps = (i >> TSH) << TSH;
    if (TSH < 9) {
        #pragma unroll
        for (int k = 1; k < 8; ++k) {
            float2 w = g_tw[k * ps];
            if (DIR < 0) w.y = -w.y;
            a[k] = cmulf(a[k], w);
        }
    }
    int base = (i & (s - 1)) + (ps << 3);
    #pragma unroll
    for (int k = 0; k < 8; ++k) dst[SWZ(base + (k << TSH))] = a[k];
}

__global__ __launch_bounds__(512) void fft_conv8_kernel() {
    extern __shared__ float2 sm[];
    float2* S0 = sm;
    float2* S1 = sm + NFFT;
    int d  = blockIdx.x & (DDIM - 1);
    int i  = threadIdx.x;
    float2* sig = g_zT + (size_t)blockIdx.x * NFFT;
    float2 a[8];

    #pragma unroll
    for (int j = 0; j < 8; ++j) a[j] = sig[i + j * 512];
    bfly8<1>(a); stage_tw_store<1, 0>(S0, a, i);
    __syncthreads();
    #pragma unroll
    for (int j = 0; j < 8; ++j) a[j] = S0[SWZ(i + j * 512)];
    bfly8<1>(a); stage_tw_store<1, 3>(S1, a, i);
    __syncthreads();
    #pragma unroll
    for (int j = 0; j < 8; ++j) a[j] = S1[SWZ(i + j * 512)];
    bfly8<1>(a); stage_tw_store<1, 6>(S0, a, i);
    __syncthreads();
    #pragma unroll
    for (int j = 0; j < 8; ++j) a[j] = S0[SWZ(i + j * 512)];
    bfly8<1>(a); stage_tw_store<1, 9>(S1, a, i);
    __syncthreads();

    const float2* kf = g_Kf + (d << 12);
    #pragma unroll
    for (int j = 0; j < 8; ++j) {
        int m = i + j * 512;
        a[j] = cmulf(S1[SWZ(m)], kf[m]);
    }
    bfly8<-1>(a); stage_tw_store<-1, 0>(S0, a, i);
    __syncthreads();
    #pragma unroll
    for (int j = 0; j < 8; ++j) a[j] = S0[SWZ(i + j * 512)];
    bfly8<-1>(a); stage_tw_store<-1, 3>(S1, a, i);
    __syncthreads();
    #pragma unroll
    for (int j = 0; j < 8; ++j) a[j] = S1[SWZ(i + j * 512)];
    bfly8<-1>(a); stage_tw_store<-1, 6>(S0, a, i);
    __syncthreads();
    #pragma unroll
    for (int j = 0; j < 8; ++j) a[j] = S0[SWZ(i + j * 512)];
    bfly8<-1>(a);
    #pragma unroll
    for (int k = 0; k < 8; ++k) sig[i + k * 512] = a[k];
}

// ---------------- untranspose + split Re/Im + D*x ----------------
__global__ __launch_bounds__(256) void t2_kernel(const float* __restrict__ x,
                                                 const float* __restrict__ Dp,
                                                 float* __restrict__ y) {
    __shared__ float2 tile[32][33];
    int b4 = blockIdx.z;
    int d0 = blockIdx.x << 5, l0 = blockIdx.y << 5;
    int tid = threadIdx.x;
    const float4* zT4 = (const float4*)g_zT;
    #pragma unroll
    for (int u = 0; u < 2; ++u) {
        int m = tid + (u << 8);
        int dd = m >> 4, lp = m & 15;
        float4 v = zT4[(((b4 * DDIM) + d0 + dd) * NFFT + l0 + 2 * lp) >> 1];
        tile[2 * lp][dd]     = make_float2(v.x, v.y);
        tile[2 * lp + 1][dd] = make_float2(v.z, v.w);
    }
    __syncthreads();
    {
        int l = tid >> 3, d4 = tid & 7;
        const float4* x4 = (const float4*)x;
        const float4* D4 = (const float4*)Dp;
        float4 DD = D4[(d0 >> 2) + d4];
        int base0 = ((b4 * NFFT) + l0 + l) * (DDIM / 4) + (d0 >> 2) + d4;
        int base1 = base0 + 4 * NFFT * (DDIM / 4);
        float4 X0 = x4[base0], X1 = x4[base1];
        float2 t0 = tile[l][4 * d4 + 0];
        float2 t1 = tile[l][4 * d4 + 1];
        float2 t2 = tile[l][4 * d4 + 2];
        float2 t3 = tile[l][4 * d4 + 3];
        float4* y4 = (float4*)y;
        y4[base0] = make_float4(t0.x + DD.x * X0.x, t1.x + DD.y * X0.y,
                                t2.x + DD.z * X0.z, t3.x + DD.w * X0.w);
        y4[base1] = make_float4(t0.y + DD.x * X1.x, t1.y + DD.y * X1.y,
                                t2.y + DD.z * X1.z, t3.y + DD.w * X1.w);
    }
}

// ---------------- launcher ----------------
extern "C" void kernel_launch(void* const* d_in, const int* in_sizes, int n_in,
                              void* d_out, int out_size) {
    const float*  x   = (const float*)d_in[0];
    const float2* lam = (const float2*)d_in[1];
    const float2* P   = (const float2*)d_in[2];
    const float2* B   = (const float2*)d_in[3];
    const float2* C   = (const float2*)d_in[4];
    const float*  Dp  = (const float*)d_in[5];
    const float*  ld  = (const float*)d_in[6];
    float* y = (float*)d_out;

    cudaFuncSetAttribute(fft_conv8_kernel,
                         cudaFuncAttributeMaxDynamicSharedMemorySize,
                         2 * NFFT * sizeof(float2));

    tw_init_kernel<<<8, 512>>>();
    weight_kernel<<<DDIM * HDIM / 256, 256>>>(lam, P, B, C);
    kf_kernel<<<dim3(8, DDIM), 256>>>(lam, ld);
    kf_nyq_kernel<<<DDIM, HDIM>>>(ld);

    dim3 tb(256);
    t1_kernel<<<dim3(DDIM / 32, NFFT / 32, NB4), tb>>>(x);
    fft_conv8_kernel<<<NB4 * DDIM, 512, 2 * NFFT * sizeof(float2)>>>();
    t2_kernel<<<dim3(DDIM / 32, NFFT / 32, NB4), tb>>>(x, Dp, y);
}

// round 4
// speedup vs baseline: 1.6861x; 1.0177x over previous
#include <cuda_runtime.h>
#include <math.h>

#define NFFT 4096
#define DDIM 256
#define HDIM 64
#define NB4  4   // BATCH/2 packed complex batches

typedef unsigned long long u64;

// ---------------- device scratch ----------------
__device__ float2 g_tw[NFFT];                 // e^{-2*pi*i*k/N}
__device__ float2 g_Kf[DDIM * NFFT];          // Hermitian kernel spectrum / N
__device__ float2 g_zT[NB4 * DDIM * NFFT];    // packed transposed signals

// ---------------- f32x2 packed helpers ----------------
__device__ __forceinline__ u64 pk2(float a, float b) {
    u64 r; asm("mov.b64 %0,{%1,%2};" : "=l"(r) : "f"(a), "f"(b)); return r;
}
__device__ __forceinline__ void upk2(u64 v, float& a, float& b) {
    asm("mov.b64 {%0,%1},%2;" : "=f"(a), "=f"(b) : "l"(v));
}
__device__ __forceinline__ u64 fma2(u64 a, u64 b, u64 c) {
    u64 d; asm("fma.rn.f32x2 %0,%1,%2,%3;" : "=l"(d) : "l"(a), "l"(b), "l"(c)); return d;
}
__device__ __forceinline__ u64 add2(u64 a, u64 b) {
    u64 d; asm("add.rn.f32x2 %0,%1,%2;" : "=l"(d) : "l"(a), "l"(b)); return d;
}

// ---------------- twiddle table ----------------
__global__ void tw_init_kernel() {
    int k = blockIdx.x * blockDim.x + threadIdx.x;
    if (k < NFFT) {
        double ang = -6.283185307179586476925286766559 * (double)k / (double)NFFT;
        g_tw[k] = make_float2((float)cos(ang), (float)sin(ang));
    }
}

// ---------------- fused: weights + Hermitian kernel spectrum + Nyquist ----------------
// g-form: g = 2(1-z)/((1+z)*delta), k.. = sum_h w../(g-lam_h)
// at = (2/u)*(k00 - k01*k10/(1+k11)); l in [0,2048); Nyquist handled by block x=0.
__global__ __launch_bounds__(256) void kf_kernel(
    const float2* __restrict__ lam, const float2* __restrict__ P,
    const float2* __restrict__ B,   const float2* __restrict__ C,
    const float* __restrict__ log_delta)
{
    __shared__ float2 slam[HDIM];
    __shared__ float2 snl[HDIM];
    __shared__ float4 sA[HDIM], sB[HDIM], sC[HDIM];
    __shared__ float2 sW[HDIM];
    int d = blockIdx.y;
    int tid = threadIdx.x;

    if (tid < HDIM) slam[tid] = lam[tid];
    __syncthreads();
    if (tid < HDIM) {
        float2 L = slam[tid];
        float best = 3.4e38f; int bi = tid;
        #pragma unroll 8
        for (int j = 0; j < HDIM; ++j) {
            float2 M = slam[j];
            float dx = M.x - L.x, dy = M.y + L.y;   // |lam_j - conj(lam_h)|^2
            float e = dx * dx + dy * dy;
            if (e < best) { best = e; bi = j; }
        }
        float2 c  = C[(d << 6) + tid];
        float2 c2 = C[(d << 6) | bi];
        float chx = 0.5f * (c.x + c2.x);
        float chy = 0.5f * (c.y - c2.y);           // Chat = (C_h + conj(C_hbar))/2
        float2 b = B[(d << 6) + tid];
        float2 p = P[tid];
        float w00x = chx * b.x - chy * b.y, w00y = chx * b.y + chy * b.x;
        float w01x = chx * p.x - chy * p.y, w01y = chx * p.y + chy * p.x;
        float w10x = p.x * b.x + p.y * b.y, w10y = p.x * b.y - p.y * b.x;
        float w11  = p.x * p.x + p.y * p.y;
        sA[tid] = make_float4(w00x, w00x, -w00y, w00y);
        sB[tid] = make_float4(w01x, w01x, -w01y, w01y);
        sC[tid] = make_float4(w10x, w10x, -w10y, w10y);
        sW[tid] = make_float2(w11, w11);
        snl[tid] = make_float2(-L.x, -L.y);
    }
    __syncthreads();

    float delta = __expf(log_delta[d]);

    // Nyquist bin (z = -1): at = 0.5*delta*sum_h Re(w00), written once
    if (blockIdx.x == 0 && tid == 0) {
        float s = 0.0f;
        #pragma unroll
        for (int h = 0; h < HDIM; ++h) s += sA[h].x;
        g_Kf[(d << 12) + 2048] = make_float2(0.5f * delta * s * (1.0f / (float)NFFT), 0.0f);
    }

    int l = blockIdx.x * 256 + tid;            // [0, 2048)
    float2 t = g_tw[l];
    float zr = t.x, zi = -t.y;                 // z = e^{+2*pi*i*l/N}
    float ux = 1.0f + zr, uy = zi;             // u = 1+z (never 0 for l<2048)
    float vx = 2.0f - 2.0f * zr, vy = -2.0f * zi;
    float udx = ux * delta, udy = uy * delta;
    float di = __fdividef(1.0f, udx * udx + udy * udy);
    float gx = (vx * udx + vy * udy) * di;     // g = v/(u*delta)
    float gy = (vy * udx - vx * udy) * di;
    u64 g2 = pk2(gx, gy);

    u64 s00 = 0ull, s01 = 0ull, s10 = 0ull, s11 = 0ull;
    const u64* pnl        = (const u64*)snl;
    const ulonglong2* pA  = (const ulonglong2*)sA;
    const ulonglong2* pB  = (const ulonglong2*)sB;
    const ulonglong2* pC  = (const ulonglong2*)sC;
    const u64* pW         = (const u64*)sW;
    #pragma unroll 16
    for (int h = 0; h < HDIM; ++h) {
        u64 q = add2(g2, pnl[h]);
        float qx, qy; upk2(q, qx, qy);
        float im = __fdividef(1.0f, qx * qx + qy * qy);
        float rr = qx * im, ri = -qy * im;     // 1/(g-lam) = (rr, ri)
        u64 rA = pk2(rr, ri);
        u64 rB = pk2(ri, rr);
        ulonglong2 A = pA[h];  s00 = fma2(A.x, rA, s00); s00 = fma2(A.y, rB, s00);
        ulonglong2 Bv = pB[h]; s01 = fma2(Bv.x, rA, s01); s01 = fma2(Bv.y, rB, s01);
        ulonglong2 Cv = pC[h]; s10 = fma2(Cv.x, rA, s10); s10 = fma2(Cv.y, rB, s10);
        s11 = fma2(pW[h], rA, s11);
    }
    float s00x, s00y, s01x, s01y, s10x, s10y, s11x, s11y;
    upk2(s00, s00x, s00y); upk2(s01, s01x, s01y);
    upk2(s10, s10x, s10y); upk2(s11, s11x, s11y);

    float nx  = s01x * s10x - s01y * s10y;
    float ny  = s01x * s10y + s01y * s10x;
    float dnx = 1.0f + s11x, dny = s11y;
    float ddi = __fdividef(1.0f, dnx * dnx + dny * dny);
    float cx  = (nx * dnx + ny * dny) * ddi;
    float cy  = (ny * dnx - nx * dny) * ddi;
    float k0x = s00x - cx, k0y = s00y - cy;
    float ui  = __fdividef(2.0f, ux * ux + uy * uy);
    float ax  = (k0x * ux + k0y * uy) * ui;
    float ay  = (k0y * ux - k0x * uy) * ui;
    const float sc = 1.0f / (float)NFFT;       // fold 1/N of inverse FFT
    ax *= sc; ay *= sc;
    if (l == 0) ay = 0.0f;
    g_Kf[(d << 12) + l] = make_float2(ax, ay);
    if (l > 0)
        g_Kf[(d << 12) + (NFFT - l)] = make_float2(ax, -ay);
}

// ---------------- transpose (B,L,D) -> packed (B4,D,L) complex ----------------
__global__ __launch_bounds__(256) void t1_kernel(const float* __restrict__ x) {
    __shared__ float2 tile[32][33];
    int b4 = blockIdx.z;
    int d0 = blockIdx.x << 5, l0 = blockIdx.y << 5;
    int tid = threadIdx.x;
    const float4* x4 = (const float4*)x;
    {
        int l = tid >> 3, d4 = tid & 7;
        int base0 = ((b4 * NFFT) + l0 + l) * (DDIM / 4) + (d0 >> 2) + d4;
        int base1 = base0 + 4 * NFFT * (DDIM / 4);
        float4 A  = x4[base0];
        float4 Bv = x4[base1];
        tile[l][4 * d4 + 0] = make_float2(A.x, Bv.x);
        tile[l][4 * d4 + 1] = make_float2(A.y, Bv.y);
        tile[l][4 * d4 + 2] = make_float2(A.z, Bv.z);
        tile[l][4 * d4 + 3] = make_float2(A.w, Bv.w);
    }
    __syncthreads();
    float4* zT4 = (float4*)g_zT;
    #pragma unroll
    for (int u = 0; u < 2; ++u) {
        int m = tid + (u << 8);
        int dd = m >> 4, lp = m & 15;
        float2 t0 = tile[2 * lp][dd];
        float2 t1 = tile[2 * lp + 1][dd];
        zT4[(((b4 * DDIM) + d0 + dd) * NFFT + l0 + 2 * lp) >> 1]
            = make_float4(t0.x, t0.y, t1.x, t1.y);
    }
}

// ---------------- radix-8 Stockham FFT helpers ----------------
__device__ __forceinline__ float2 cmulf(float2 a, float2 b) {
    return make_float2(a.x * b.x - a.y * b.y, a.x * b.y + a.y * b.x);
}
#define SWZ(m) ((m) ^ (((m) >> 4) & 7))

template<int DIR>
__device__ __forceinline__ void bfly8(float2 a[8]) {
    const float S2 = 0.70710678118654752440f;
    float2 b0, b1, b2, b3, c0, c1, c2, c3;
    b0.x=a[0].x+a[4].x; b0.y=a[0].y+a[4].y;  c0.x=a[0].x-a[4].x; c0.y=a[0].y-a[4].y;
    b1.x=a[1].x+a[5].x; b1.y=a[1].y+a[5].y;  c1.x=a[1].x-a[5].x; c1.y=a[1].y-a[5].y;
    b2.x=a[2].x+a[6].x; b2.y=a[2].y+a[6].y;  c2.x=a[2].x-a[6].x; c2.y=a[2].y-a[6].y;
    b3.x=a[3].x+a[7].x; b3.y=a[3].y+a[7].y;  c3.x=a[3].x-a[7].x; c3.y=a[3].y-a[7].y;
    float2 tc1, tc2, tc3;
    if (DIR > 0) {
        tc1 = make_float2(S2 * (c1.x + c1.y),  S2 * (c1.y - c1.x));
        tc2 = make_float2(c2.y, -c2.x);
        tc3 = make_float2(S2 * (c3.y - c3.x), -S2 * (c3.x + c3.y));
    } else {
        tc1 = make_float2(S2 * (c1.x - c1.y),  S2 * (c1.y + c1.x));
        tc2 = make_float2(-c2.y, c2.x);
        tc3 = make_float2(-S2 * (c3.x + c3.y), S2 * (c3.x - c3.y));
    }
    float2 p0 = make_float2(b0.x + b2.x, b0.y + b2.y);
    float2 p1 = make_float2(b0.x - b2.x, b0.y - b2.y);
    float2 p2 = make_float2(b1.x + b3.x, b1.y + b3.y);
    float2 p3 = make_float2(b1.x - b3.x, b1.y - b3.y);
    float2 q0 = make_float2(c0.x + tc2.x, c0.y + tc2.y);
    float2 q1 = make_float2(c0.x - tc2.x, c0.y - tc2.y);
    float2 q2 = make_float2(tc1.x + tc3.x, tc1.y + tc3.y);
    float2 q3 = make_float2(tc1.x - tc3.x, tc1.y - tc3.y);
    float2 jp3 = (DIR > 0) ? make_float2(p3.y, -p3.x) : make_float2(-p3.y, p3.x);
    float2 jq3 = (DIR > 0) ? make_float2(q3.y, -q3.x) : make_float2(-q3.y, q3.x);
    a[0] = make_float2(p0.x + p2.x, p0.y + p2.y);
    a[4] = make_float2(p0.x - p2.x, p0.y - p2.y);
    a[2] = make_float2(p1.x + jp3.x, p1.y + jp3.y);
    a[6] = make_float2(p1.x - jp3.x, p1.y - jp3.y);
    a[1] = make_float2(q0.x + q2.x, q0.y + q2.y);
    a[5] = make_float2(q0.x - q2.x, q0.y - q2.y);
    a[3] = make_float2(q1.x + jq3.x, q1.y + jq3.y);
    a[7] = make_float2(q1.x - jq3.x, q1.y - jq3.y);
}

template<int DIR, int TSH>
__device__ __forceinline__ void stage_tw_store(float2* dst, float2 a[8], int i) {
    const int s = 1 << TSH;
    int ps = (i >> TSH) << TSH;
    if (TSH < 9) {
        #pragma unroll
        for (int k = 1; k < 8; ++k) {
            float2 w = g_tw[k * ps];
            if (DIR < 0) w.y = -w.y;
            a[k] = cmulf(a[k], w);
        }
    }
    int base = (i & (s - 1)) + (ps << 3);
    #pragma unroll
    for (int k = 0; k < 8; ++k) dst[SWZ(base + (k << TSH))] = a[k];
}

__global__ __launch_bounds__(512) void fft_conv8_kernel() {
    extern __shared__ float2 sm[];
    float2* S0 = sm;
    float2* S1 = sm + NFFT;
    int d  = blockIdx.x & (DDIM - 1);
    int i  = threadIdx.x;
    float2* sig = g_zT + (size_t)blockIdx.x * NFFT;
    float2 a[8];

    // ---- forward ----
    #pragma unroll
    for (int j = 0; j < 8; ++j) a[j] = sig[i + j * 512];
    bfly8<1>(a); stage_tw_store<1, 0>(S0, a, i);
    __syncthreads();
    #pragma unroll
    for (int j = 0; j < 8; ++j) a[j] = S0[SWZ(i + j * 512)];
    bfly8<1>(a); stage_tw_store<1, 3>(S1, a, i);
    __syncthreads();
    #pragma unroll
    for (int j = 0; j < 8; ++j) a[j] = S1[SWZ(i + j * 512)];
    bfly8<1>(a); stage_tw_store<1, 6>(S0, a, i);
    __syncthreads();
    #pragma unroll
    for (int j = 0; j < 8; ++j) a[j] = S0[SWZ(i + j * 512)];
    bfly8<1>(a);
    // F3 (TSH=9): no twiddles; a[j] IS natural-order bin (i + j*512).
    // Apply Kf in registers — no smem round trip between fwd and inv.
    {
        const float2* kf = g_Kf + (d << 12);
        #pragma unroll
        for (int j = 0; j < 8; ++j) a[j] = cmulf(a[j], __ldg(&kf[i + j * 512]));
    }
    // ---- inverse ----
    bfly8<-1>(a); stage_tw_store<-1, 0>(S1, a, i);   // S1: no race with F3 reads of S0
    __syncthreads();
    #pragma unroll
    for (int j = 0; j < 8; ++j) a[j] = S1[SWZ(i + j * 512)];
    bfly8<-1>(a); stage_tw_store<-1, 3>(S0, a, i);
    __syncthreads();
    #pragma unroll
    for (int j = 0; j < 8; ++j) a[j] = S0[SWZ(i + j * 512)];
    bfly8<-1>(a); stage_tw_store<-1, 6>(S1, a, i);
    __syncthreads();
    #pragma unroll
    for (int j = 0; j < 8; ++j) a[j] = S1[SWZ(i + j * 512)];
    bfly8<-1>(a);
    #pragma unroll
    for (int k = 0; k < 8; ++k) sig[i + k * 512] = a[k];
}

// ---------------- untranspose + split Re/Im + D*x ----------------
__global__ __launch_bounds__(256) void t2_kernel(const float* __restrict__ x,
                                                 const float* __restrict__ Dp,
                                                 float* __restrict__ y) {
    __shared__ float2 tile[32][33];
    int b4 = blockIdx.z;
    int d0 = blockIdx.x << 5, l0 = blockIdx.y << 5;
    int tid = threadIdx.x;
    const float4* zT4 = (const float4*)g_zT;
    #pragma unroll
    for (int u = 0; u < 2; ++u) {
        int m = tid + (u << 8);
        int dd = m >> 4, lp = m & 15;
        float4 v = zT4[(((b4 * DDIM) + d0 + dd) * NFFT + l0 + 2 * lp) >> 1];
        tile[2 * lp][dd]     = make_float2(v.x, v.y);
        tile[2 * lp + 1][dd] = make_float2(v.z, v.w);
    }
    __syncthreads();
    {
        int l = tid >> 3, d4 = tid & 7;
        const float4* x4 = (const float4*)x;
        const float4* D4 = (const float4*)Dp;
        float4 DD = D4[(d0 >> 2) + d4];
        int base0 = ((b4 * NFFT) + l0 + l) * (DDIM / 4) + (d0 >> 2) + d4;
        int base1 = base0 + 4 * NFFT * (DDIM / 4);
        float4 X0 = x4[base0], X1 = x4[base1];
        float2 t0 = tile[l][4 * d4 + 0];
        float2 t1 = tile[l][4 * d4 + 1];
        float2 t2 = tile[l][4 * d4 + 2];
        float2 t3 = tile[l][4 * d4 + 3];
        float4* y4 = (float4*)y;
        y4[base0] = make_float4(t0.x + DD.x * X0.x, t1.x + DD.y * X0.y,
                                t2.x + DD.z * X0.z, t3.x + DD.w * X0.w);
        y4[base1] = make_float4(t0.y + DD.x * X1.x, t1.y + DD.y * X1.y,
                                t2.y + DD.z * X1.z, t3.y + DD.w * X1.w);
    }
}

// ---------------- launcher ----------------
extern "C" void kernel_launch(void* const* d_in, const int* in_sizes, int n_in,
                              void* d_out, int out_size) {
    const float*  x   = (const float*)d_in[0];
    const float2* lam = (const float2*)d_in[1];
    const float2* P   = (const float2*)d_in[2];
    const float2* B   = (const float2*)d_in[3];
    const float2* C   = (const float2*)d_in[4];
    const float*  Dp  = (const float*)d_in[5];
    const float*  ld  = (const float*)d_in[6];
    float* y = (float*)d_out;

    cudaFuncSetAttribute(fft_conv8_kernel,
                         cudaFuncAttributeMaxDynamicSharedMemorySize,
                         2 * NFFT * sizeof(float2));

    tw_init_kernel<<<8, 512>>>();
    kf_kernel<<<dim3(8, DDIM), 256>>>(lam, P, B, C, ld);

    dim3 tb(256);
    t1_kernel<<<dim3(DDIM / 32, NFFT / 32, NB4), tb>>>(x);
    fft_conv8_kernel<<<NB4 * DDIM, 512, 2 * NFFT * sizeof(float2)>>>();
    t2_kernel<<<dim3(DDIM / 32, NFFT / 32, NB4), tb>>>(x, Dp, y);
}